// round 9
// baseline (speedup 1.0000x reference)
#include <cuda_runtime.h>

namespace {
constexpr int T_  = 1024;
constexpr int S_  = 64;
constexpr int D_  = 256;
constexpr int TP_ = 8;
constexpr int C_  = 65;   // 2*H*N_K + 1
}

__device__ __forceinline__ unsigned pack_sgnabs(int v) {
    unsigned a = (unsigned)(v < 0 ? -v : v);
    return a | (v < 0 ? 0x80000000u : 0u);
}

__global__ __launch_bounds__(256, 3) void crit_main(
    const int*   __restrict__ sta_loc,
    const int*   __restrict__ nei_loc,
    const int*   __restrict__ rand_numbers,
    const float* __restrict__ sta_emb,
    const float* __restrict__ nei_emb,
    const float* __restrict__ mask,
    const float* __restrict__ rand_vals,
    const float* __restrict__ t_rand,
    float*       __restrict__ out)
{
    __shared__ float4   s_buf[2][1024];    // 2 x 16KB nei_emb chunk (16 rows x 256 f)
    __shared__ float    s_sta[D_];
    __shared__ float    s_mask[S_];
    __shared__ float    s_cs[S_][TP_];
    __shared__ unsigned s_neiT[TP_][68];   // transposed, padded: (sign<<31)|abs
    __shared__ float    s_PT[TP_][68];     // sqrt(|eu|*mask) * B[s][p]
    __shared__ float    s_swc[68];         // sqrt(|eu|*mask)/128
    __shared__ unsigned s_cnc[C_][TP_];    // packed (sign<<31)|abs
    __shared__ float    s_loss[C_][TP_];
    __shared__ float    s_red[8];
    __shared__ float    s_t32p[16];
    __shared__ float    s_red2[8];
    __shared__ float    s_rv[TP_];
    __shared__ float    s_rl[TP_];

    const int t    = blockIdx.x;
    const int tid  = threadIdx.x;
    const int lane = tid & 31;
    const int warp = tid >> 5;
    const int p    = tid & 7;

    // ---------------- issue chunk 0 & 1 cp.async IMMEDIATELY ----------------
    const float4* src4 = (const float4*)(nei_emb + (size_t)t * (S_ * D_));
    {
        unsigned d0 = (unsigned)__cvta_generic_to_shared(&s_buf[0][0]) + tid * 64u;
        unsigned d1 = (unsigned)__cvta_generic_to_shared(&s_buf[1][0]) + tid * 64u;
        #pragma unroll
        for (int k = 0; k < 4; k++)
            asm volatile("cp.async.cg.shared.global [%0], [%1], 16;"
                         :: "r"(d0 + k * 16u), "l"(src4 + tid * 4 + k));
        asm volatile("cp.async.commit_group;" ::: "memory");
        #pragma unroll
        for (int k = 0; k < 4; k++)
            asm volatile("cp.async.cg.shared.global [%0], [%1], 16;"
                         :: "r"(d1 + k * 16u), "l"(src4 + 1024 + tid * 4 + k));
        asm volatile("cp.async.commit_group;" ::: "memory");
    }

    // ---------------- inline int64 detection (per-warp) ----------------
    int dlo = sta_loc[2 * lane];
    int dhi = sta_loc[2 * lane + 1];
    unsigned bmll = __ballot_sync(0xffffffffu, dhi == (dlo >> 31));
    const int str = (bmll == 0xffffffffu) ? 2 : 1;

    // ---------------- small loads ----------------
    float sv  = sta_emb[(size_t)t * D_ + tid];
    int   nb0 = nei_loc[((size_t)t * (S_*TP_) + tid) * str];
    int   nb1 = nei_loc[((size_t)t * (S_*TP_) + 256 + tid) * str];
    int   rn  = rand_numbers[((size_t)t * 256 + tid) * str];
    int   sl  = sta_loc[((size_t)t * TP_ + p) * str];
    if (tid < S_)  s_mask[tid] = mask[(size_t)t * S_ + tid];
    float tr = 0.f;
    if (tid < TP_) {
        s_rv[tid] = rand_vals[(size_t)t * TP_ + tid];
        tr        = t_rand[t];
    }

    // ---------------- D: cos_sn + packed nei ----------------
    {
        int aa = sl < 0 ? -sl : sl;
        #pragma unroll
        for (int it = 0; it < 2; it++) {
            int idx = tid + it * 256;
            int nb  = it ? nb1 : nb0;
            int s = idx >> 3;
            int sg = ((nb ^ sl) < 0);
            int na = nb < 0 ? -nb : nb;
            unsigned x = (unsigned)(na ^ aa) + 1u;
            int v  = __clz((int)x) - 16;
            int iv = sg ? -v : v;
            s_cs[s][p]   = (float)iv * 0.0625f;
            s_neiT[p][s] = (unsigned)na | (nb < 0 ? 0x80000000u : 0u);
        }
    }

    // ---------------- E: cnc packed; F constants stay in registers ----------------
    unsigned ca0, ca1, sflip;
    {
        int k = tid >> 4, c = tid >> 3;   // c = 2k+j
        int r = sl ^ (1 << k) ^ (rn & ((1 << k) - 1));
        ca0 = pack_sgnabs(r);
        ca1 = pack_sgnabs(-r);
        sflip = (ca0 ^ ca1) & 0x80000000u;
        s_cnc[c][p]      = ca0;
        s_cnc[c + 33][p] = ca1;
        if (tid < TP_) s_cnc[32][tid] = pack_sgnabs(sl);
    }

    // sta into smem + |sta|^2 partial reduce
    s_sta[tid] = sv;
    float ns = sv * sv;
    #pragma unroll
    for (int o = 16; o; o >>= 1) ns += __shfl_xor_sync(0xffffffffu, ns, o);
    if (lane == 0) s_red[warp] = ns;

    // ---------------- chunked pipeline over s ----------------
    const int slot = (warp << 1) | (lane >> 4);   // 0..15: row within chunk
    const int li   = lane & 15;
    float acc0 = 0.f, acc1 = 0.f, t32 = 0.f;
    const int c0 = tid >> 3;
    const int4*   nt  = (const int4*)&s_neiT[p][0];
    const float4* ptv = (const float4*)&s_PT[p][0];
    const float4* swp = (const float4*)s_swc;

    #pragma unroll
    for (int ch = 0; ch < 4; ch++) {
        asm volatile("cp.async.wait_group 1;" ::: "memory");
        __syncthreads();   // chunk ch buffer + (ch==0: all prologue smem) visible

        // ---- dot + C' for rows ch*16 .. ch*16+15 ----
        {
            const float4* nr = &s_buf[ch & 1][slot * 64];
            const float4* sa = (const float4*)s_sta;
            float dot = 0.f, nn = 0.f;
            #pragma unroll
            for (int j = 0; j < 4; j++) {
                float4 bb = nr[li + 16 * j];
                float4 a  = sa[li + 16 * j];
                dot = fmaf(a.x, bb.x, dot); dot = fmaf(a.y, bb.y, dot);
                dot = fmaf(a.z, bb.z, dot); dot = fmaf(a.w, bb.w, dot);
                nn  = fmaf(bb.x, bb.x, nn); nn  = fmaf(bb.y, bb.y, nn);
                nn  = fmaf(bb.z, bb.z, nn); nn  = fmaf(bb.w, bb.w, nn);
            }
            #pragma unroll
            for (int o = 1; o < 16; o <<= 1) {
                dot += __shfl_xor_sync(0xffffffffu, dot, o);
                nn  += __shfl_xor_sync(0xffffffffu, nn,  o);
            }
            if (li == 0) {
                int row = ch * 16 + slot;
                float tot = s_red[0] + s_red[1] + s_red[2] + s_red[3]
                          + s_red[4] + s_red[5] + s_red[6] + s_red[7];
                float rns = rsqrtf(tot);
                float eu  = dot * rsqrtf(nn) * rns;
                float4 caf = *(const float4*)&s_cs[row][0];
                float4 cbf = *(const float4*)&s_cs[row][4];
                float sum = caf.x + caf.y + caf.z + caf.w
                          + cbf.x + cbf.y + cbf.z + cbf.w;
                float w   = fabsf(eu) * s_mask[row];
                float sqw = sqrtf(w);
                s_swc[row] = sqw * 0.0078125f;
                float cm  = fmaf(sum, 0.125f, -eu);
                float csv[8] = {caf.x, caf.y, caf.z, caf.w, cbf.x, cbf.y, cbf.z, cbf.w};
                #pragma unroll
                for (int pp = 0; pp < 8; pp++)
                    s_PT[pp][row] = sqw * fmaf(csv[pp], -0.125f, cm);
                t32 = fmaf(w * cm, cm, t32);
            }
        }
        __syncthreads();   // P/swc ready; buf[ch&1] fully consumed

        // ---- prefetch chunk ch+2 into the vacated buffer ----
        if (ch < 2) {
            unsigned dst = (unsigned)__cvta_generic_to_shared(&s_buf[ch & 1][0]) + tid * 64u;
            const float4* s = src4 + (ch + 2) * 1024 + tid * 4;
            #pragma unroll
            for (int k = 0; k < 4; k++)
                asm volatile("cp.async.cg.shared.global [%0], [%1], 16;"
                             :: "r"(dst + k * 16u), "l"(s + k));
        }
        asm volatile("cp.async.commit_group;" ::: "memory");  // uniform group count

        // ---- F partial for this chunk (overlaps the cp.async above) ----
        #pragma unroll
        for (int k = 0; k < 4; k++) {
            int idx = ch * 4 + k;
            int4   nv = nt[idx];
            float4 Pv = ptv[idx];
            float4 sw = swp[idx];
            #pragma unroll
            for (int i = 0; i < 4; i++) {
                unsigned ne = (i == 0) ? (unsigned)nv.x : (i == 1) ? (unsigned)nv.y
                            : (i == 2) ? (unsigned)nv.z : (unsigned)nv.w;
                float P   = (i == 0) ? Pv.x : (i == 1) ? Pv.y : (i == 2) ? Pv.z : Pv.w;
                float swv = (i == 0) ? sw.x : (i == 1) ? sw.y : (i == 2) ? sw.z : sw.w;
                unsigned xr = ca0 ^ ne;
                unsigned x1 = (xr & 0x1FFFFu) + 1u;
                float uf = (float)(__clz((int)x1) - 16);
                float us0 = __int_as_float(__float_as_int(uf) ^ (xr & 0x80000000u));
                float us1 = __int_as_float(__float_as_int(us0) ^ sflip);
                float h0 = fmaf(us0, swv, P);
                float h1 = fmaf(us1, swv, P);
                acc0 = fmaf(h0, h0, acc0);
                acc1 = fmaf(h1, h1, acc1);
            }
        }
    }

    // ---------------- wrap-up ----------------
    s_loss[c0][p]      = acc0;
    s_loss[c0 + 33][p] = acc1;
    if (li == 0) s_t32p[slot] = t32;
    __syncthreads();

    // ---------------- G: argmin, selection, outputs ----------------
    if (tid < TP_) {
        // loss[32] (p-independent) from leader partials
        float l32 = 0.f;
        #pragma unroll
        for (int j = 0; j < 16; j++) l32 += s_t32p[j];
        s_loss[32][tid] = l32;
        // partial mask sums for lth
        float m8 = 0.f;
        #pragma unroll
        for (int j = 0; j < 8; j++) m8 += s_mask[tid * 8 + j];
        s_red2[tid] = m8;

        float best = l32 < s_loss[0][tid] ? 0.f : 0.f;  // placeholder, real loop below
        best = s_loss[0][tid]; int bc = 0;
        #pragma unroll
        for (int c = 1; c < C_; c++) {
            float v = (c == 32) ? l32 : s_loss[c][tid];
            if (v < best) { best = v; bc = c; }       // first-occurrence argmin
        }
        float rv = s_rv[tid]; int rank = 0;
        #pragma unroll
        for (int q = 0; q < 8; q++) {
            float o = s_rv[q];
            rank += (o < rv) || (o == rv && q < tid); // stable argsort rank
        }
        int selg = (tr < 0.8f);
        int ci = (rank < 4) ? (selg ? bc : 32) : 32;
        unsigned pk = s_cnc[ci][tid];
        int val = (pk & 0x80000000u) ? -(int)(pk & 0x7fffffffu) : (int)pk;
        out[(size_t)t * TP_ + tid] = (float)val;
        s_rl[tid] = (ci == 32) ? l32 : s_loss[ci][tid];
        __syncwarp(0x000000ffu);
        if (tid == 0) {
            float rl = 0.f, lth = 0.f;
            #pragma unroll
            for (int q = 0; q < 8; q++) { rl += s_rl[q]; lth += s_red2[q]; }
            out[(size_t)T_ * TP_ + t] = rl * 0.125f / (lth + 1e-12f);
        }
    }
}

extern "C" void kernel_launch(void* const* d_in, const int* in_sizes, int n_in,
                              void* d_out, int out_size) {
    (void)in_sizes; (void)n_in; (void)out_size;
    const int*   sta_loc      = (const int*)  d_in[0];
    const int*   nei_loc      = (const int*)  d_in[1];
    const int*   rand_numbers = (const int*)  d_in[2];
    const float* sta_emb      = (const float*)d_in[3];
    const float* nei_emb      = (const float*)d_in[4];
    const float* mask         = (const float*)d_in[5];
    const float* rand_vals    = (const float*)d_in[6];
    const float* t_rand       = (const float*)d_in[7];
    float* out = (float*)d_out;

    crit_main<<<T_, 256>>>(sta_loc, nei_loc, rand_numbers,
                           sta_emb, nei_emb, mask, rand_vals, t_rand, out);
}